// round 5
// baseline (speedup 1.0000x reference)
#include <cuda_runtime.h>
#include <mma.h>
#include <cstdint>

using namespace nvcuda;

#define B_  4
#define S_  2048
#define D_  1024
#define H_  16
#define DK_ 64

// Scratch (allocation-free rule: __device__ globals).
__device__ float g_Q [(size_t)B_*S_*D_];
__device__ float g_K [(size_t)B_*S_*D_];
__device__ float g_V [(size_t)B_*S_*D_];
__device__ float g_AO[(size_t)B_*S_*D_];
__device__ float g_RS[(size_t)B_*H_*S_];   // row sums of unnormalized P

#define TF32(x) wmma::__float_to_tf32(x)

__device__ __forceinline__ void cpasync16(uint32_t saddr, const float* g) {
    asm volatile("cp.async.cg.shared.global [%0], [%1], 16;" :: "r"(saddr), "l"(g));
}
__device__ __forceinline__ void cpasync_commit() {
    asm volatile("cp.async.commit_group;");
}
__device__ __forceinline__ void cpasync_wait0() {
    asm volatile("cp.async.wait_group 0;");
}

// ---------------------------------------------------------------------------
// tf32 NT GEMM: C = A @ B^T + bias. A [M,K], B [N,K], both row-major.
// BM=BN=128, BK=32, 256 thr = 8 warps (2x4), warp tile 64x32.
// tf32-rounded once at smem store. round_out -> tf32-rounded outputs.
// ---------------------------------------------------------------------------
#define LDP 36

__global__ __launch_bounds__(256) void gemm_nt_tf32(
    const float* __restrict__ A, const float* __restrict__ Bm,
    const float* __restrict__ bias, float* __restrict__ C,
    int K, int lda, int ldb, int ldc, int round_out)
{
    const int tid  = threadIdx.x;
    const int w    = tid >> 5, lane = tid & 31;
    const int wm   = w >> 2, wn = w & 3;

    const size_t m0 = (size_t)blockIdx.y * 128;
    const size_t n0 = (size_t)blockIdx.x * 128;

    __shared__ float As[128 * LDP];
    __shared__ float Bs[128 * LDP];
    __shared__ float Cs[8][16 * 20];

    wmma::fragment<wmma::accumulator, 16, 16, 8, float> c[4][2];
#pragma unroll
    for (int i = 0; i < 4; i++)
#pragma unroll
        for (int j = 0; j < 2; j++) wmma::fill_fragment(c[i][j], 0.f);

    for (int k0 = 0; k0 < K; k0 += 32) {
        float4 av[4], bv[4];
#pragma unroll
        for (int it = 0; it < 4; it++) {
            int idx = tid + 256 * it;
            int row = idx >> 3, c4 = idx & 7;
            av[it] = *(const float4*)(A  + (m0 + row) * (size_t)lda + k0 + c4 * 4);
            bv[it] = *(const float4*)(Bm + (n0 + row) * (size_t)ldb + k0 + c4 * 4);
        }
        __syncthreads();
#pragma unroll
        for (int it = 0; it < 4; it++) {
            int idx = tid + 256 * it;
            int row = idx >> 3, c4 = idx & 7;
            float4 a = av[it], b = bv[it];
            a.x = TF32(a.x); a.y = TF32(a.y); a.z = TF32(a.z); a.w = TF32(a.w);
            b.x = TF32(b.x); b.y = TF32(b.y); b.z = TF32(b.z); b.w = TF32(b.w);
            *(float4*)&As[row * LDP + c4 * 4] = a;
            *(float4*)&Bs[row * LDP + c4 * 4] = b;
        }
        __syncthreads();

#pragma unroll
        for (int ks = 0; ks < 4; ks++) {
            wmma::fragment<wmma::matrix_a, 16, 16, 8, wmma::precision::tf32, wmma::row_major> a[4];
            wmma::fragment<wmma::matrix_b, 16, 16, 8, wmma::precision::tf32, wmma::col_major> b[2];
#pragma unroll
            for (int i = 0; i < 4; i++)
                wmma::load_matrix_sync(a[i], &As[(64 * wm + 16 * i) * LDP + ks * 8], LDP);
#pragma unroll
            for (int j = 0; j < 2; j++)
                wmma::load_matrix_sync(b[j], &Bs[(32 * wn + 16 * j) * LDP + ks * 8], LDP);
#pragma unroll
            for (int i = 0; i < 4; i++)
#pragma unroll
                for (int j = 0; j < 2; j++)
                    wmma::mma_sync(c[i][j], a[i], b[j], c[i][j]);
        }
        __syncthreads();
    }

    float* buf = Cs[w];
#pragma unroll
    for (int i = 0; i < 4; i++) {
#pragma unroll
        for (int j = 0; j < 2; j++) {
            wmma::store_matrix_sync(buf, c[i][j], 20, wmma::mem_row_major);
            __syncwarp();
            const int rr = lane >> 1, ch = (lane & 1) * 8;
            const size_t gr = m0 + 64 * wm + 16 * i + rr;
            const size_t gc = n0 + 32 * wn + 16 * j + ch;
            float4 v0 = *(float4*)&buf[rr * 20 + ch];
            float4 v1 = *(float4*)&buf[rr * 20 + ch + 4];
            v0.x += bias[gc + 0]; v0.y += bias[gc + 1];
            v0.z += bias[gc + 2]; v0.w += bias[gc + 3];
            v1.x += bias[gc + 4]; v1.y += bias[gc + 5];
            v1.z += bias[gc + 6]; v1.w += bias[gc + 7];
            if (round_out) {
                v0.x = TF32(v0.x); v0.y = TF32(v0.y); v0.z = TF32(v0.z); v0.w = TF32(v0.w);
                v1.x = TF32(v1.x); v1.y = TF32(v1.y); v1.z = TF32(v1.z); v1.w = TF32(v1.w);
            }
            *(float4*)(C + gr * (size_t)ldc + gc)     = v0;
            *(float4*)(C + gr * (size_t)ldc + gc + 4) = v1;
            __syncwarp();
        }
    }
}

// ---------------------------------------------------------------------------
// Fused attention per (q-tile 128, head). Q/K/V pre-rounded tf32.
// Q fragments register-resident; K/V via cp.async double buffers.
// Smem (floats): Ps [128*72] @0 (Q staging at init, O staging at end),
//   Kb[2] [64*72] @9216, Vb[2] [64*72] @18432.  Total 27648 fl = 110592 B.
// Warp grid 4x2 (wm=w>>1, wn=w&1), warp tile 32x32 for both gemms.
// ---------------------------------------------------------------------------
#define FA_SMEM_FLOATS 27648
#define FA_SMEM_BYTES  (FA_SMEM_FLOATS * 4)
#define PS_OFF 0
#define KB_OFF 9216
#define VB_OFF 18432
#define KVSTRIDE 4608

__global__ __launch_bounds__(256, 2) void fused_attn(
    const float* __restrict__ Q, const float* __restrict__ K,
    const float* __restrict__ V, float* __restrict__ P,
    float* __restrict__ rsum, float* __restrict__ AO)
{
    extern __shared__ float sm[];
    float* Ps = sm + PS_OFF;
    const uint32_t smem_u32 = (uint32_t)__cvta_generic_to_shared(sm);

    const int tid = threadIdx.x, w = tid >> 5;
    const int wm = w >> 1, wn = w & 1;       // 4x2 grid, 32x32 warp tiles
    const int bh = blockIdx.y, b = bh >> 4, h = bh & 15;
    const int q0 = blockIdx.x * 128;
    const int prow = tid >> 4;               // coalesced passes: base row
    const int pc4  = tid & 15;               // float4 column

    const float* Qb = Q + (size_t)b * S_ * D_ + h * DK_;
    const float* Kb = K + (size_t)b * S_ * D_ + h * DK_;
    const float* Vb = V + (size_t)b * S_ * D_ + h * DK_;
    float* Pb = P + (size_t)bh * S_ * S_;

    // copy-thread mapping for K/V chunks (64 rows x 16 float4)
    const int crow = tid >> 4;               // base row 0..15 (+16 per it)
    const int cc4  = tid & 15;

    // ---- Stage Q tile into Ps, then preload Q fragments to registers ----
#pragma unroll
    for (int it = 0; it < 8; it++) {
        int idx = tid + 256 * it;
        int row = idx >> 4, c4 = idx & 15;
        *(float4*)&Ps[row * 72 + c4 * 4] =
            *(const float4*)(Qb + (size_t)(q0 + row) * D_ + c4 * 4);
    }
    __syncthreads();

    wmma::fragment<wmma::matrix_a, 16, 16, 8, wmma::precision::tf32, wmma::row_major> Qf[8][2];
#pragma unroll
    for (int ks = 0; ks < 8; ks++)
#pragma unroll
        for (int i = 0; i < 2; i++)
            wmma::load_matrix_sync(Qf[ks][i], &Ps[(32 * wm + 16 * i) * 72 + ks * 8], 72);

    float rs[8];
#pragma unroll
    for (int i = 0; i < 8; i++) rs[i] = 0.f;

    wmma::fragment<wmma::accumulator, 16, 16, 8, float> c_o[2][2];
#pragma unroll
    for (int i = 0; i < 2; i++)
#pragma unroll
        for (int j = 0; j < 2; j++) wmma::fill_fragment(c_o[i][j], 0.f);

    // ---- prologue: cp.async chunk 0 into buffer 0 ----
#pragma unroll
    for (int it = 0; it < 4; it++) {
        int row = crow + 16 * it;
        cpasync16(smem_u32 + (KB_OFF + row * 72 + cc4 * 4) * 4,
                  Kb + (size_t)row * D_ + cc4 * 4);
        cpasync16(smem_u32 + (VB_OFF + row * 72 + cc4 * 4) * 4,
                  Vb + (size_t)row * D_ + cc4 * 4);
    }
    cpasync_commit();

    for (int kc = 0; kc < 32; kc++) {
        const int cur = kc & 1;
        float* Kc = sm + KB_OFF + cur * KVSTRIDE;
        float* Vc = sm + VB_OFF + cur * KVSTRIDE;

        cpasync_wait0();
        __syncthreads();   // data ready; prev PV done (so other buffers free)

        if (kc + 1 < 32) {
            const int nxt = 1 - cur;
#pragma unroll
            for (int it = 0; it < 4; it++) {
                int row = crow + 16 * it;
                cpasync16(smem_u32 + (KB_OFF + nxt * KVSTRIDE + row * 72 + cc4 * 4) * 4,
                          Kb + (size_t)((kc + 1) * 64 + row) * D_ + cc4 * 4);
                cpasync16(smem_u32 + (VB_OFF + nxt * KVSTRIDE + row * 72 + cc4 * 4) * 4,
                          Vb + (size_t)((kc + 1) * 64 + row) * D_ + cc4 * 4);
            }
            cpasync_commit();
        }

        // ---- S = Q @ Kc^T : warp tile 32x32, Q from registers ----
        wmma::fragment<wmma::accumulator, 16, 16, 8, float> c_s[2][2];
#pragma unroll
        for (int i = 0; i < 2; i++)
#pragma unroll
            for (int j = 0; j < 2; j++) wmma::fill_fragment(c_s[i][j], 0.f);
#pragma unroll
        for (int ks = 0; ks < 8; ks++) {
            wmma::fragment<wmma::matrix_b, 16, 16, 8, wmma::precision::tf32, wmma::col_major> bb[2];
#pragma unroll
            for (int j = 0; j < 2; j++)
                wmma::load_matrix_sync(bb[j], &Kc[(32 * wn + 16 * j) * 72 + ks * 8], 72);
#pragma unroll
            for (int i = 0; i < 2; i++)
#pragma unroll
                for (int j = 0; j < 2; j++)
                    wmma::mma_sync(c_s[i][j], Qf[ks][i], bb[j], c_s[i][j]);
        }

        // S frags -> Ps
#pragma unroll
        for (int i = 0; i < 2; i++)
#pragma unroll
            for (int j = 0; j < 2; j++)
                wmma::store_matrix_sync(&Ps[(32 * wm + 16 * i) * 72 + 32 * wn + 16 * j],
                                        c_s[i][j], 72, wmma::mem_row_major);
        __syncthreads();

        // ---- exp pass: Ps -> gmem P + tf32-rounded Ps + reg rowsums ----
#pragma unroll
        for (int it = 0; it < 8; it++) {
            int row = prow + 16 * it;
            float4 v = *(float4*)&Ps[row * 72 + pc4 * 4];
            v.x = __expf(v.x * 0.125f); v.y = __expf(v.y * 0.125f);
            v.z = __expf(v.z * 0.125f); v.w = __expf(v.w * 0.125f);
            float s = v.x + v.y + v.z + v.w;
            s += __shfl_xor_sync(0xffffffffu, s, 1);
            s += __shfl_xor_sync(0xffffffffu, s, 2);
            s += __shfl_xor_sync(0xffffffffu, s, 4);
            s += __shfl_xor_sync(0xffffffffu, s, 8);
            rs[it] += s;
            *(float4*)(Pb + (size_t)(q0 + row) * S_ + kc * 64 + pc4 * 4) = v;
            v.x = TF32(v.x); v.y = TF32(v.y); v.z = TF32(v.z); v.w = TF32(v.w);
            *(float4*)&Ps[row * 72 + pc4 * 4] = v;
        }
        __syncthreads();

        // ---- O += Ps(128x64) @ Vc(64x64) ----
#pragma unroll
        for (int ks = 0; ks < 8; ks++) {
            wmma::fragment<wmma::matrix_a, 16, 16, 8, wmma::precision::tf32, wmma::row_major> a2[2];
            wmma::fragment<wmma::matrix_b, 16, 16, 8, wmma::precision::tf32, wmma::row_major> b2[2];
#pragma unroll
            for (int i = 0; i < 2; i++)
                wmma::load_matrix_sync(a2[i], &Ps[(32 * wm + 16 * i) * 72 + ks * 8], 72);
#pragma unroll
            for (int j = 0; j < 2; j++)
                wmma::load_matrix_sync(b2[j], &Vc[(ks * 8) * 72 + 32 * wn + 16 * j], 72);
#pragma unroll
            for (int i = 0; i < 2; i++)
#pragma unroll
                for (int j = 0; j < 2; j++)
                    wmma::mma_sync(c_o[i][j], a2[i], b2[j], c_o[i][j]);
        }
    }

    __syncthreads();   // PV done; Ps reusable for O staging

    // rowsums -> gmem
    if ((tid & 15) == 0) {
#pragma unroll
        for (int it = 0; it < 8; it++)
            rsum[(size_t)bh * S_ + q0 + prow + 16 * it] = rs[it];
    }

    // O frags -> Ps staging
#pragma unroll
    for (int i = 0; i < 2; i++)
#pragma unroll
        for (int j = 0; j < 2; j++)
            wmma::store_matrix_sync(&Ps[(32 * wm + 16 * i) * 72 + 32 * wn + 16 * j],
                                    c_o[i][j], 72, wmma::mem_row_major);
    __syncthreads();

    // Coalesced AO write: scale by 1/rowsum, tf32-round for out-proj
#pragma unroll
    for (int it = 0; it < 8; it++) {
        int row = prow + 16 * it;
        const float inv = 1.0f / rs[it];
        float4 v = *(float4*)&Ps[row * 72 + pc4 * 4];
        v.x = TF32(v.x * inv); v.y = TF32(v.y * inv);
        v.z = TF32(v.z * inv); v.w = TF32(v.w * inv);
        *(float4*)(AO + ((size_t)b * S_ + q0 + row) * D_ + h * DK_ + pc4 * 4) = v;
    }
}

// ---------------------------------------------------------------------------
// Rescale P rows by 1/rowsum. One block per row (2048 floats).
// ---------------------------------------------------------------------------
__global__ __launch_bounds__(256) void rescale_rows(
    float* __restrict__ P, const float* __restrict__ rsum)
{
    const size_t row = blockIdx.x;
    const float inv = 1.0f / rsum[row];
    float4* p = (float4*)(P + row * 2048);
    const int t = threadIdx.x;
    float4 a = p[t];
    float4 c = p[t + 256];
    a.x *= inv; a.y *= inv; a.z *= inv; a.w *= inv;
    c.x *= inv; c.y *= inv; c.z *= inv; c.w *= inv;
    p[t]       = a;
    p[t + 256] = c;
}

// ---------------------------------------------------------------------------
extern "C" void kernel_launch(void* const* d_in, const int* in_sizes, int n_in,
                              void* d_out, int out_size)
{
    const float* query = (const float*)d_in[0];
    const float* key_  = (const float*)d_in[1];
    const float* value = (const float*)d_in[2];
    const float* Wq = (const float*)d_in[3];
    const float* bq = (const float*)d_in[4];
    const float* Wk = (const float*)d_in[5];
    const float* bk = (const float*)d_in[6];
    const float* Wv = (const float*)d_in[7];
    const float* bv = (const float*)d_in[8];
    const float* Wo = (const float*)d_in[9];
    const float* bo = (const float*)d_in[10];

    float* out  = (float*)d_out;
    float* attn = out + (size_t)B_ * S_ * D_;

    float *Qp, *Kp, *Vp, *AOp, *RSp;
    cudaGetSymbolAddress((void**)&Qp,  g_Q);
    cudaGetSymbolAddress((void**)&Kp,  g_K);
    cudaGetSymbolAddress((void**)&Vp,  g_V);
    cudaGetSymbolAddress((void**)&AOp, g_AO);
    cudaGetSymbolAddress((void**)&RSp, g_RS);

    cudaFuncSetAttribute(fused_attn,
                         cudaFuncAttributeMaxDynamicSharedMemorySize,
                         FA_SMEM_BYTES);

    const dim3 blk(256);

    gemm_nt_tf32<<<dim3(8, 64), blk>>>(query, Wq, bq, Qp, 1024, 1024, 1024, 1024, 1);
    gemm_nt_tf32<<<dim3(8, 64), blk>>>(key_,  Wk, bk, Kp, 1024, 1024, 1024, 1024, 1);
    gemm_nt_tf32<<<dim3(8, 64), blk>>>(value, Wv, bv, Vp, 1024, 1024, 1024, 1024, 1);

    fused_attn<<<dim3(16, 64), blk, FA_SMEM_BYTES>>>(Qp, Kp, Vp, attn, RSp, AOp);

    rescale_rows<<<B_ * H_ * S_, blk>>>(attn, RSp);

    gemm_nt_tf32<<<dim3(8, 64), blk>>>(AOp, Wo, bo, out, 1024, 1024, 1024, 1024, 0);
}